// round 2
// baseline (speedup 1.0000x reference)
#include <cuda_runtime.h>

// Inputs (metadata order):
//  0 Rotation[9] 1 center[2] 2 bbox[4] 3 bbox_3d[6] 4 ER[9] 5 et[3] 6 K[9]
//  7 kx[1] 8 ky[1] 9 beta[1] 10 t[3] 11 R[4] 12 s[3] 13 s_cls[3]
// Output: 6 floats [overall, pixel_center, world_center, rotation, scale_bbox, scale_cls]

__device__ __forceinline__ float frcp(float x) {
    float r; asm("rcp.approx.ftz.f32 %0, %1;" : "=f"(r) : "f"(x)); return r;
}
__device__ __forceinline__ float frsq(float x) {
    float r; asm("rsqrt.approx.ftz.f32 %0, %1;" : "=f"(r) : "f"(x)); return r;
}

// adjugate/det inverse, reciprocal via MUFU approx
__device__ __forceinline__ void inv3x3(const float m[9], float inv[9]) {
    float c00 =  (m[4]*m[8] - m[5]*m[7]);
    float c01 = -(m[3]*m[8] - m[5]*m[6]);
    float c02 =  (m[3]*m[7] - m[4]*m[6]);
    float c10 = -(m[1]*m[8] - m[2]*m[7]);
    float c11 =  (m[0]*m[8] - m[2]*m[6]);
    float c12 = -(m[0]*m[7] - m[1]*m[6]);
    float c20 =  (m[1]*m[5] - m[2]*m[4]);
    float c21 = -(m[0]*m[5] - m[2]*m[3]);
    float c22 =  (m[0]*m[4] - m[1]*m[3]);
    float id = frcp(m[0]*c00 + m[1]*c01 + m[2]*c02);
    inv[0] = c00*id; inv[1] = c10*id; inv[2] = c20*id;
    inv[3] = c01*id; inv[4] = c11*id; inv[5] = c21*id;
    inv[6] = c02*id; inv[7] = c12*id; inv[8] = c22*id;
}

__global__ void overall_loss_kernel(
    const float* __restrict__ Rotation, const float* __restrict__ center,
    const float* __restrict__ bbox,     const float* __restrict__ bbox_3d,
    const float* __restrict__ ER,       const float* __restrict__ et,
    const float* __restrict__ K,        const float* __restrict__ kx,
    const float* __restrict__ ky,       const float* __restrict__ beta,
    const float* __restrict__ t,        const float* __restrict__ Rq,
    const float* __restrict__ s,        const float* __restrict__ s_cls,
    float* __restrict__ out)
{
    const float FRAME_W = 1920.0f, FRAME_H = 1080.0f, COEF = 0.2f;
    const float INV_W = 1.0f / 1920.0f, INV_H = 1.0f / 1080.0f;

    // ================= LOAD WAVE: issue every global load up front =========
    float rot_in[9], er[9], kk[9];
    #pragma unroll
    for (int i = 0; i < 9; i++) rot_in[i] = Rotation[i];
    #pragma unroll
    for (int i = 0; i < 9; i++) er[i] = ER[i];
    #pragma unroll
    for (int i = 0; i < 9; i++) kk[i] = K[i];
    float cen0 = center[0], cen1 = center[1];
    float bb0 = bbox[0], bb1 = bbox[1], bb2 = bbox[2], bb3 = bbox[3];
    float b3[6];
    #pragma unroll
    for (int i = 0; i < 6; i++) b3[i] = bbox_3d[i];
    float e0 = et[0], e1 = et[1], e2 = et[2];
    float kxv = kx[0], kyv = ky[0], be = beta[0];
    float t0 = t[0], t1 = t[1], t2 = t[2];
    float q0 = Rq[0], q1 = Rq[1], q2 = Rq[2], q3 = Rq[3];
    float s0 = s[0], s1 = s[1], s2 = s[2];
    float sc0 = s_cls[0], sc1 = s_cls[1], sc2 = s_cls[2];

    // ================= quaternion -> rotation matrix ========================
    float qn = frsq(q0*q0 + q1*q1 + q2*q2 + q3*q3);
    float x0 = q0*qn, x1 = q1*qn, x2 = q2*qn, x3 = q3*qn;
    float Rm[9];
    Rm[0] = 1.0f - 2.0f*(x1*x1 + x2*x2);
    Rm[1] = 2.0f*(x0*x1 - x2*x3);
    Rm[2] = 2.0f*(x0*x2 + x1*x3);
    Rm[3] = 2.0f*(x0*x1 + x2*x3);
    Rm[4] = 1.0f - 2.0f*(x0*x0 + x2*x2);
    Rm[5] = 2.0f*(x1*x2 - x0*x3);
    Rm[6] = 2.0f*(x0*x2 - x1*x3);
    Rm[7] = 2.0f*(x1*x2 + x0*x3);
    Rm[8] = 1.0f - 2.0f*(x0*x0 + x1*x1);

    // ext = [[ER,0],[et,1]]; ext_inv = [[Ai,0],[-et@Ai,1]], Ai = ER^{-1}
    float Ai[9];
    inv3x3(er, Ai);

    // ================= 8 corners -> pixel min/max ===========================
    float minx =  3.4e38f, maxx = -3.4e38f;
    float miny =  3.4e38f, maxy = -3.4e38f;
    #pragma unroll
    for (int i = 0; i < 8; i++) {
        float cx = b3[(i >> 2) & 1]       * s0;
        float cy = b3[2 + ((i >> 1) & 1)] * s1;
        float cz = b3[4 + (i & 1)]        * s2;
        float wx = Rm[0]*cx + Rm[1]*cy + Rm[2]*cz + t0;
        float wy = Rm[3]*cx + Rm[4]*cy + Rm[5]*cz + t1;
        float wz = Rm[6]*cx + Rm[7]*cy + Rm[8]*cz + t2;
        float dx = wx - e0, dy = wy - e1, dz = wz - e2;
        float c0 = dx*Ai[0] + dy*Ai[3] + dz*Ai[6];
        float c1 = dx*Ai[1] + dy*Ai[4] + dz*Ai[7];
        float c2 = dx*Ai[2] + dy*Ai[5] + dz*Ai[8];
        float iz = frcp(c2);
        float nx = c0 * iz, ny = c1 * iz;
        float px = kk[0]*nx + kk[1]*ny + kk[2];
        float py = kk[3]*nx + kk[4]*ny + kk[5];
        minx = fminf(minx, px); maxx = fmaxf(maxx, px);
        miny = fminf(miny, py); maxy = fmaxf(maxy, py);
    }
    float b2d0 = minx * INV_W, b2d1 = maxx * INV_W;
    float b2d2 = miny * INV_H, b2d3 = maxy * INV_H;

    // ================= world-center ========================================
    float cc_raw0 = be * kxv * FRAME_W;
    float cc_raw1 = be * kyv * FRAME_H;
    float cc_raw2 = be;
    float Ki[9];
    inv3x3(kk, Ki);
    float cc0 = Ki[0]*cc_raw0 + Ki[1]*cc_raw1 + Ki[2]*cc_raw2;
    float cc1 = Ki[3]*cc_raw0 + Ki[4]*cc_raw1 + Ki[5]*cc_raw2;
    float cc2 = Ki[6]*cc_raw0 + Ki[7]*cc_raw1 + Ki[8]*cc_raw2;
    float w0 = cc0*er[0] + cc1*er[3] + cc2*er[6] + e0;
    float w1 = cc0*er[1] + cc1*er[4] + cc2*er[7] + e1;
    float w2 = cc0*er[2] + cc1*er[5] + cc2*er[8] + e2;

    // ================= losses ==============================================
    float pixel_center = 0.5f * (fabsf(kxv - cen0) + fabsf(kyv - cen1));
    float world_center = (fabsf(w0 - t0) + fabsf(w1 - t1) + fabsf(w2 - t2)) * (1.0f/3.0f);

    float rot = 0.0f;
    #pragma unroll
    for (int i = 0; i < 3; i++) {
        #pragma unroll
        for (int j = 0; j < 3; j++) {
            float m = er[i*3+0]*Rm[0*3+j] + er[i*3+1]*Rm[1*3+j] + er[i*3+2]*Rm[2*3+j];
            float d = rot_in[i*3+j] - m;
            rot += d * d;
        }
    }
    rot *= (1.0f/9.0f);

    float sb = 0.25f * (fabsf(b2d0 - bb0) + fabsf(b2d1 - bb1) +
                        fabsf(b2d2 - bb2) + fabsf(b2d3 - bb3));
    float sc = (fabsf(s0 - sc0) + fabsf(s1 - sc1) + fabsf(s2 - sc2)) * (1.0f/3.0f);

    float overall = COEF * (pixel_center + world_center + rot + sb + sc);

    // vectorized stores (d_out is harness-allocated, 16B-aligned)
    float4 o0 = make_float4(overall, pixel_center, world_center, rot);
    float2 o1 = make_float2(sb, sc);
    *reinterpret_cast<float4*>(out)     = o0;
    *reinterpret_cast<float2*>(out + 4) = o1;
}

extern "C" void kernel_launch(void* const* d_in, const int* in_sizes, int n_in,
                              void* d_out, int out_size) {
    (void)in_sizes; (void)n_in; (void)out_size;
    overall_loss_kernel<<<1, 1>>>(
        (const float*)d_in[0],  (const float*)d_in[1],  (const float*)d_in[2],
        (const float*)d_in[3],  (const float*)d_in[4],  (const float*)d_in[5],
        (const float*)d_in[6],  (const float*)d_in[7],  (const float*)d_in[8],
        (const float*)d_in[9],  (const float*)d_in[10], (const float*)d_in[11],
        (const float*)d_in[12], (const float*)d_in[13],
        (float*)d_out);
}

// round 3
// speedup vs baseline: 1.4545x; 1.4545x over previous
#include <cuda_runtime.h>

// Inputs (metadata order):
//  0 Rotation[9] 1 center[2] 2 bbox[4] 3 bbox_3d[6] 4 ER[9] 5 et[3] 6 K[9]
//  7 kx[1] 8 ky[1] 9 beta[1] 10 t[3] 11 R[4] 12 s[3] 13 s_cls[3]
// Output: 6 floats [overall, pixel_center, world_center, rotation, scale_bbox, scale_cls]

__device__ __forceinline__ float frcp(float x) {
    float r; asm("rcp.approx.ftz.f32 %0, %1;" : "=f"(r) : "f"(x)); return r;
}
__device__ __forceinline__ float frsq(float x) {
    float r; asm("rsqrt.approx.ftz.f32 %0, %1;" : "=f"(r) : "f"(x)); return r;
}

// adjugate/det inverse, reciprocal via MUFU approx
__device__ __forceinline__ void inv3x3(const float m[9], float inv[9]) {
    float c00 =  (m[4]*m[8] - m[5]*m[7]);
    float c01 = -(m[3]*m[8] - m[5]*m[6]);
    float c02 =  (m[3]*m[7] - m[4]*m[6]);
    float c10 = -(m[1]*m[8] - m[2]*m[7]);
    float c11 =  (m[0]*m[8] - m[2]*m[6]);
    float c12 = -(m[0]*m[7] - m[1]*m[6]);
    float c20 =  (m[1]*m[5] - m[2]*m[4]);
    float c21 = -(m[0]*m[5] - m[2]*m[3]);
    float c22 =  (m[0]*m[4] - m[1]*m[3]);
    float id = frcp(m[0]*c00 + m[1]*c01 + m[2]*c02);
    inv[0] = c00*id; inv[1] = c10*id; inv[2] = c20*id;
    inv[3] = c01*id; inv[4] = c11*id; inv[5] = c21*id;
    inv[6] = c02*id; inv[7] = c12*id; inv[8] = c22*id;
}

// butterfly min/max over 8-lane groups (lanes 8..31 mirror 0..7, so result valid on all lanes)
__device__ __forceinline__ float wmin8(float v) {
    v = fminf(v, __shfl_xor_sync(0xffffffffu, v, 4));
    v = fminf(v, __shfl_xor_sync(0xffffffffu, v, 2));
    v = fminf(v, __shfl_xor_sync(0xffffffffu, v, 1));
    return v;
}
__device__ __forceinline__ float wmax8(float v) {
    v = fmaxf(v, __shfl_xor_sync(0xffffffffu, v, 4));
    v = fmaxf(v, __shfl_xor_sync(0xffffffffu, v, 2));
    v = fmaxf(v, __shfl_xor_sync(0xffffffffu, v, 1));
    return v;
}

__global__ void __launch_bounds__(32, 1) overall_loss_kernel(
    const float* __restrict__ Rotation, const float* __restrict__ center,
    const float* __restrict__ bbox,     const float* __restrict__ bbox_3d,
    const float* __restrict__ ER,       const float* __restrict__ et,
    const float* __restrict__ K,        const float* __restrict__ kx,
    const float* __restrict__ ky,       const float* __restrict__ beta,
    const float* __restrict__ t,        const float* __restrict__ Rq,
    const float* __restrict__ s,        const float* __restrict__ s_cls,
    float* __restrict__ out)
{
    const float FRAME_W = 1920.0f, FRAME_H = 1080.0f, COEF = 0.2f;
    const float INV_W = 1.0f / 1920.0f, INV_H = 1.0f / 1080.0f;

    const int lane = threadIdx.x;
    const int ci   = lane & 7;   // corner index (duplicated across 8-lane groups)

    // ================= LOAD WAVE (broadcast; all lanes same addrs) =========
    float rot_in[9], er[9], kk[9];
    #pragma unroll
    for (int i = 0; i < 9; i++) rot_in[i] = Rotation[i];
    #pragma unroll
    for (int i = 0; i < 9; i++) er[i] = ER[i];
    #pragma unroll
    for (int i = 0; i < 9; i++) kk[i] = K[i];
    float cen0 = center[0], cen1 = center[1];
    float bb0 = bbox[0], bb1 = bbox[1], bb2 = bbox[2], bb3 = bbox[3];
    float b3[6];
    #pragma unroll
    for (int i = 0; i < 6; i++) b3[i] = bbox_3d[i];
    float e0 = et[0], e1 = et[1], e2 = et[2];
    float kxv = kx[0], kyv = ky[0], be = beta[0];
    float t0 = t[0], t1 = t[1], t2 = t[2];
    float q0 = Rq[0], q1 = Rq[1], q2 = Rq[2], q3 = Rq[3];
    float s0 = s[0], s1 = s[1], s2 = s[2];
    float sc0 = s_cls[0], sc1 = s_cls[1], sc2 = s_cls[2];

    // ================= quaternion -> rotation matrix ========================
    float qn = frsq(q0*q0 + q1*q1 + q2*q2 + q3*q3);
    float x0 = q0*qn, x1 = q1*qn, x2 = q2*qn, x3 = q3*qn;
    float Rm[9];
    Rm[0] = 1.0f - 2.0f*(x1*x1 + x2*x2);
    Rm[1] = 2.0f*(x0*x1 - x2*x3);
    Rm[2] = 2.0f*(x0*x2 + x1*x3);
    Rm[3] = 2.0f*(x0*x1 + x2*x3);
    Rm[4] = 1.0f - 2.0f*(x0*x0 + x2*x2);
    Rm[5] = 2.0f*(x1*x2 - x0*x3);
    Rm[6] = 2.0f*(x0*x2 - x1*x3);
    Rm[7] = 2.0f*(x1*x2 + x0*x3);
    Rm[8] = 1.0f - 2.0f*(x0*x0 + x1*x1);

    // ext = [[ER,0],[et,1]]; ext_inv = [[Ai,0],[-et@Ai,1]], Ai = ER^{-1}
    float Ai[9];
    inv3x3(er, Ai);

    // ================= corner 'ci' -> pixel (one per lane) ==================
    float cx = b3[(ci >> 2) & 1]       * s0;
    float cy = b3[2 + ((ci >> 1) & 1)] * s1;
    float cz = b3[4 + (ci & 1)]        * s2;
    float wx = Rm[0]*cx + Rm[1]*cy + Rm[2]*cz + t0;
    float wy = Rm[3]*cx + Rm[4]*cy + Rm[5]*cz + t1;
    float wz = Rm[6]*cx + Rm[7]*cy + Rm[8]*cz + t2;
    float dx = wx - e0, dy = wy - e1, dz = wz - e2;
    float c0 = dx*Ai[0] + dy*Ai[3] + dz*Ai[6];
    float c1 = dx*Ai[1] + dy*Ai[4] + dz*Ai[7];
    float c2 = dx*Ai[2] + dy*Ai[5] + dz*Ai[8];
    float iz = frcp(c2);
    float nx = c0 * iz, ny = c1 * iz;
    float px = kk[0]*nx + kk[1]*ny + kk[2];
    float py = kk[3]*nx + kk[4]*ny + kk[5];

    // 8-way reduction via butterfly shuffles (valid on every lane)
    float minx = wmin8(px), maxx = wmax8(px);
    float miny = wmin8(py), maxy = wmax8(py);

    float b2d0 = minx * INV_W, b2d1 = maxx * INV_W;
    float b2d2 = miny * INV_H, b2d3 = maxy * INV_H;

    // ================= world-center ========================================
    float cc_raw0 = be * kxv * FRAME_W;
    float cc_raw1 = be * kyv * FRAME_H;
    float cc_raw2 = be;
    float Ki[9];
    inv3x3(kk, Ki);
    float cc0 = Ki[0]*cc_raw0 + Ki[1]*cc_raw1 + Ki[2]*cc_raw2;
    float cc1 = Ki[3]*cc_raw0 + Ki[4]*cc_raw1 + Ki[5]*cc_raw2;
    float cc2 = Ki[6]*cc_raw0 + Ki[7]*cc_raw1 + Ki[8]*cc_raw2;
    float w0 = cc0*er[0] + cc1*er[3] + cc2*er[6] + e0;
    float w1 = cc0*er[1] + cc1*er[4] + cc2*er[7] + e1;
    float w2 = cc0*er[2] + cc1*er[5] + cc2*er[8] + e2;

    // ================= losses ==============================================
    float pixel_center = 0.5f * (fabsf(kxv - cen0) + fabsf(kyv - cen1));
    float world_center = (fabsf(w0 - t0) + fabsf(w1 - t1) + fabsf(w2 - t2)) * (1.0f/3.0f);

    float rot = 0.0f;
    #pragma unroll
    for (int i = 0; i < 3; i++) {
        #pragma unroll
        for (int j = 0; j < 3; j++) {
            float m = er[i*3+0]*Rm[0*3+j] + er[i*3+1]*Rm[1*3+j] + er[i*3+2]*Rm[2*3+j];
            float d = rot_in[i*3+j] - m;
            rot += d * d;
        }
    }
    rot *= (1.0f/9.0f);

    float sb = 0.25f * (fabsf(b2d0 - bb0) + fabsf(b2d1 - bb1) +
                        fabsf(b2d2 - bb2) + fabsf(b2d3 - bb3));
    float sc = (fabsf(s0 - sc0) + fabsf(s1 - sc1) + fabsf(s2 - sc2)) * (1.0f/3.0f);

    float overall = COEF * (pixel_center + world_center + rot + sb + sc);

    if (lane == 0) {
        *reinterpret_cast<float4*>(out)     = make_float4(overall, pixel_center, world_center, rot);
        *reinterpret_cast<float2*>(out + 4) = make_float2(sb, sc);
    }
}

extern "C" void kernel_launch(void* const* d_in, const int* in_sizes, int n_in,
                              void* d_out, int out_size) {
    (void)in_sizes; (void)n_in; (void)out_size;
    overall_loss_kernel<<<1, 32>>>(
        (const float*)d_in[0],  (const float*)d_in[1],  (const float*)d_in[2],
        (const float*)d_in[3],  (const float*)d_in[4],  (const float*)d_in[5],
        (const float*)d_in[6],  (const float*)d_in[7],  (const float*)d_in[8],
        (const float*)d_in[9],  (const float*)d_in[10], (const float*)d_in[11],
        (const float*)d_in[12], (const float*)d_in[13],
        (float*)d_out);
}